// round 3
// baseline (speedup 1.0000x reference)
#include <cuda_runtime.h>
#include <math_constants.h>

#define D_DIM   64
#define K_CODES 512
#define HW      4096
#define N_PIX   131072              // 32*64*64
#define NQ      8388608             // 32*64*64*64
#define ENC_SZ  ((long long)N_PIX * K_CODES)   // 67108864
#define SMEM_BYTES ((D_DIM * K_CODES + K_CODES) * 4)   // 133120

__device__ double g_loss_acc;

__global__ void zero_acc_kernel() { g_loss_acc = 0.0; }

__global__ void finalize_kernel(float* out_loss) {
    // loss = vq_loss + commit_loss = 2 * mean((quant - x)^2)
    *out_loss = (float)(2.0 * g_loss_acc / (double)NQ);
}

__device__ __forceinline__ void fma2(unsigned long long& acc,
                                     unsigned long long a,
                                     unsigned long long b) {
    asm("fma.rn.f32x2 %0, %1, %2, %0;" : "+l"(acc) : "l"(a), "l"(b));
}

__global__ void __launch_bounds__(512, 1) vq_kernel(
    const float* __restrict__ X, const float* __restrict__ W,
    float* __restrict__ out_q, float* __restrict__ out_enc,
    float* __restrict__ out_idx_f, int* __restrict__ out_idx_i)
{
    extern __shared__ float smem[];
    float* ws = smem;                 // transposed codebook [d][k] : 64 x 512
    float* Bs = smem + D_DIM * K_CODES; // ||e_k||^2 : 512

    const int tid = threadIdx.x;

    // Load + transpose codebook into smem (coalesced global reads).
    for (int i = tid; i < K_CODES * D_DIM; i += 512) {
        int k = i / D_DIM, d = i % D_DIM;
        ws[d * K_CODES + k] = W[i];
    }
    // ||e_k||^2, one code per thread, d ascending (match reference sum order).
    {
        int k = tid;               // 512 threads == K_CODES
        float b = 0.0f;
        #pragma unroll
        for (int d = 0; d < D_DIM; d++) {
            float w = W[k * D_DIM + d];
            b += w * w;
        }
        Bs[k] = b;
    }
    __syncthreads();

    const int p  = blockIdx.x * 512 + tid;      // pixel index over [B,H,W]
    const int bb = p >> 12;                     // batch
    const int hw = p & 4095;                    // h*64+w
    const float* xb = X + (size_t)bb * (D_DIM * HW) + hw;

    // x into registers + A = ||x||^2 (d ascending).
    float x[D_DIM];
    #pragma unroll
    for (int d = 0; d < D_DIM; d++) x[d] = xb[(size_t)d * HW];
    float A = 0.0f;
    #pragma unroll
    for (int d = 0; d < D_DIM; d++) A += x[d] * x[d];

    float best  = CUDART_INF_F;
    int   bestk = 0;

    // K in chunks of 16 codes; dot products via packed f32x2 FMA.
    for (int k0 = 0; k0 < K_CODES; k0 += 16) {
        unsigned long long acc[8];
        #pragma unroll
        for (int j = 0; j < 8; j++) acc[j] = 0ull;

        #pragma unroll
        for (int d = 0; d < D_DIM; d++) {
            unsigned long long xd2;
            asm("mov.b64 %0, {%1, %1};" : "=l"(xd2) : "f"(x[d]));
            const ulonglong2* wp =
                reinterpret_cast<const ulonglong2*>(ws + d * K_CODES + k0);
            #pragma unroll
            for (int q = 0; q < 4; q++) {
                ulonglong2 v = wp[q];
                fma2(acc[2 * q],     xd2, v.x);
                fma2(acc[2 * q + 1], xd2, v.y);
            }
        }

        // dist = (A + ||e||^2) - 2*s, fp32, same op order as reference.
        #pragma unroll
        for (int j = 0; j < 8; j++) {
            float slo = __uint_as_float((unsigned)(acc[j] & 0xffffffffull));
            float shi = __uint_as_float((unsigned)(acc[j] >> 32));
            int k = k0 + 2 * j;
            float d0 = (A + Bs[k])     - 2.0f * slo;
            float d1 = (A + Bs[k + 1]) - 2.0f * shi;
            if (d0 < best) { best = d0; bestk = k; }
            if (d1 < best) { best = d1; bestk = k + 1; }
        }
    }

    // Outputs.
    if (out_enc)   out_enc[(size_t)p * K_CODES + bestk] = 1.0f;
    if (out_idx_f) out_idx_f[p] = (float)bestk;
    if (out_idx_i) out_idx_i[p] = bestk;

    float lsum = 0.0f;
    float* qb = out_q ? (out_q + (size_t)bb * (D_DIM * HW) + hw) : nullptr;
    #pragma unroll
    for (int d = 0; d < D_DIM; d++) {
        float wv   = ws[d * K_CODES + bestk];
        float diff = wv - x[d];                // fl(q - x), as reference
        if (qb) qb[(size_t)d * HW] = x[d] + diff;  // straight-through rounding
        lsum += diff * diff;
    }
    // warp reduce + one double atomic per warp
    #pragma unroll
    for (int off = 16; off > 0; off >>= 1)
        lsum += __shfl_down_sync(0xffffffffu, lsum, off);
    if ((tid & 31) == 0) atomicAdd(&g_loss_acc, (double)lsum);
}

extern "C" void kernel_launch(void* const* d_in, const int* in_sizes, int n_in,
                              void* d_out, int out_size)
{
    const float* X = (const float*)d_in[0];
    const float* W = (const float*)d_in[1];
    float* out = (float*)d_out;

    const long long os = (long long)out_size;
    const long long FULL    = 1LL + NQ + ENC_SZ + N_PIX;   // loss,quant,enc,idx
    const long long NO_LOSS = (long long)NQ + ENC_SZ + N_PIX;

    float* p_loss = nullptr;
    float* p_q    = nullptr;
    float* p_enc  = nullptr;
    float* p_idxf = nullptr;
    int*   p_idxi = nullptr;

    if (os == FULL) {
        p_loss = out;
        p_q    = out + 1;
        p_enc  = out + 1 + NQ;
        p_idxf = out + 1 + NQ + ENC_SZ;
    } else if (os == NO_LOSS) {
        p_q    = out;
        p_enc  = out + NQ;
        p_idxf = out + NQ + ENC_SZ;
    } else if (os == NQ) {
        p_q = out;                       // quantized only
    } else if (os == N_PIX) {
        p_idxi = (int*)d_out;            // idx only (likely int32 dtype)
    } else if (os == 1) {
        p_loss = out;                    // loss only
    } else {
        // Unknown layout: assume full-tuple ordering within whatever fits.
        p_loss = out;
        p_q    = out + 1;
        if (os >= 1 + NQ + ENC_SZ) p_enc = out + 1 + NQ;
        if (os >= FULL) p_idxf = out + 1 + NQ + ENC_SZ;
    }

    cudaFuncSetAttribute(vq_kernel,
                         cudaFuncAttributeMaxDynamicSharedMemorySize,
                         SMEM_BYTES);

    zero_acc_kernel<<<1, 1>>>();
    if (p_enc)
        cudaMemsetAsync(p_enc, 0, (size_t)ENC_SZ * sizeof(float));

    vq_kernel<<<N_PIX / 512, 512, SMEM_BYTES>>>(X, W, p_q, p_enc,
                                                p_idxf, p_idxi);

    if (p_loss)
        finalize_kernel<<<1, 1>>>(p_loss);
}

// round 10
// speedup vs baseline: 1.0979x; 1.0979x over previous
#include <cuda_runtime.h>
#include <math_constants.h>
#include <cstdint>

#define D_DIM   64
#define K_CODES 512
#define HW      4096
#define N_PIX   131072              // 32*64*64
#define NQ      8388608             // 32*64*64*64
#define ENC_SZ  ((long long)N_PIX * K_CODES)   // 67108864

// ---------------- device globals (no allocation allowed) ----------------
__device__ double   g_loss_acc;
__device__ int      g_flag_cnt;
__device__ float    g_Bs[K_CODES];
__device__ __align__(16) uint32_t g_Wfrag[K_CODES * D_DIM]; // tf32 bits, B-frag order
__device__ unsigned g_list[N_PIX];

__device__ __forceinline__ uint32_t f2tf32(float f) {
    uint32_t o;
    asm("cvt.rna.tf32.f32 %0, %1;" : "=r"(o) : "f"(f));
    return o;
}

__device__ __forceinline__ void mma_tf32(float& d0, float& d1, float& d2, float& d3,
                                         uint32_t a0, uint32_t a1, uint32_t a2, uint32_t a3,
                                         uint32_t b0, uint32_t b1) {
    asm volatile(
        "mma.sync.aligned.m16n8k8.row.col.f32.tf32.tf32.f32 "
        "{%0,%1,%2,%3}, {%4,%5,%6,%7}, {%8,%9}, {%0,%1,%2,%3};"
        : "+f"(d0), "+f"(d1), "+f"(d2), "+f"(d3)
        : "r"(a0), "r"(a1), "r"(a2), "r"(a3), "r"(b0), "r"(b1));
}

// ---------------- prep kernels ----------------
__global__ void prep_bs_kernel(const float* __restrict__ W) {
    int k = threadIdx.x;             // 512 threads
    float b = 0.0f;
    #pragma unroll
    for (int d = 0; d < D_DIM; d++) { float w = W[k * D_DIM + d]; b += w * w; }
    g_Bs[k] = b;
    if (k == 0) { g_loss_acc = 0.0; g_flag_cnt = 0; }
}

// B fragment order (PTX mma.m16n8k8, B col-major 8x8 per step):
//   b0: (k = lane%4,     n = lane/4),  b1: (k = lane%4 + 4, n = lane/4)
// layout: idx = (((c*4 + j)*32 + lane)*4 + v), s = 2j + (v>>1), which = v&1
__global__ void prep_frag_kernel(const float* __restrict__ W) {
    int idx = blockIdx.x * 512 + threadIdx.x;   // 64 x 512 = 32768
    int v    = idx & 3;
    int lane = (idx >> 2) & 31;
    int j    = (idx >> 7) & 3;
    int c    = idx >> 9;
    int s  = 2 * j + (v >> 1);
    int k  = s * 8 + (lane & 3) + ((v & 1) ? 4 : 0);
    int n  = c * 8 + (lane >> 2);
    g_Wfrag[idx] = f2tf32(W[n * D_DIM + k]);
}

__global__ void finalize_kernel(float* out_loss) {
    *out_loss = (float)(2.0 * g_loss_acc / (double)NQ);
}

// ---------------- smem layout (bytes) ----------------
#define SM_W     0               // 131072 : Wfrag (tf32 bits)
#define SM_BS    131072          //   2048 : ||e||^2
#define SM_XS    133120          //  33280 : x tile tf32, [128][65]
#define SM_K1    166400          //    512 : per-pixel approx argmax
#define SM_GAP   166912          //    512 : per-pixel top-2 gap
#define SM_TOTAL 167424

// ---------------- main kernel: 128 pixels / block, 8 warps ----------------
__global__ void __launch_bounds__(256, 1)
vq_mma_kernel(const float* __restrict__ X, const float* __restrict__ W,
              float* __restrict__ out_q, float* __restrict__ out_enc,
              float* __restrict__ out_idx_f)
{
    extern __shared__ char smem[];
    uint32_t* Wf  = (uint32_t*)(smem + SM_W);
    float*    Bss = (float*)(smem + SM_BS);
    uint32_t* xs  = (uint32_t*)(smem + SM_XS);
    int*      sk1 = (int*)(smem + SM_K1);
    float*    sgp = (float*)(smem + SM_GAP);

    const int tid  = threadIdx.x;
    const int lane = tid & 31, warp = tid >> 5;
    const int tile = blockIdx.x;
    const int bidx = tile >> 5;
    const int hw0  = (tile & 31) << 7;

    // stage codebook fragments (L2-resident, coalesced 16B)
    {
        const uint4* src = (const uint4*)g_Wfrag;
        uint4* dst = (uint4*)Wf;
        #pragma unroll
        for (int i = 0; i < 32; i++) dst[tid + 256 * i] = src[tid + 256 * i];
    }
    for (int i = tid; i < K_CODES; i += 256) Bss[i] = g_Bs[i];

    // stage x tile as tf32, [m][d] stride 65 (conflict-free STS)
    const float* Xb = X + (size_t)bidx * (D_DIM * HW) + hw0;
    for (int i = tid; i < 128 * D_DIM; i += 256) {
        int d = i >> 7, m = i & 127;
        xs[m * 65 + d] = f2tf32(Xb[(size_t)d * HW + m]);
    }
    __syncthreads();

    // ---- phase 1: per-warp 16 rows x 512 codes via mma.sync tf32 ----
    {
        const int g = lane >> 2, t = lane & 3;
        const int row0 = warp * 16;
        // A fragments (m16n8k8): a0(r=g,k=t) a1(r=g+8,k=t) a2(r=g,k=t+4) a3(r=g+8,k=t+4)
        uint32_t a[8][4];
        #pragma unroll
        for (int s = 0; s < 8; s++) {
            int klo = s * 8 + t;
            a[s][0] = xs[(row0 + g)     * 65 + klo];
            a[s][1] = xs[(row0 + g + 8) * 65 + klo];
            a[s][2] = xs[(row0 + g)     * 65 + klo + 4];
            a[s][3] = xs[(row0 + g + 8) * 65 + klo + 4];
        }

        float m1lo = -CUDART_INF_F, m2lo = -CUDART_INF_F;
        float m1hi = -CUDART_INF_F, m2hi = -CUDART_INF_F;
        int   k1lo = 0, k1hi = 0;

        const uint4*  Wf4 = (const uint4*)Wf;
        const float2* Bs2 = (const float2*)Bss;

        #pragma unroll 2
        for (int c = 0; c < 64; c++) {
            uint4 bq[4];
            #pragma unroll
            for (int j = 0; j < 4; j++) bq[j] = Wf4[(c * 4 + j) * 32 + lane];

            float d0 = 0.f, d1 = 0.f, d2 = 0.f, d3 = 0.f;
            #pragma unroll
            for (int j = 0; j < 4; j++) {
                mma_tf32(d0, d1, d2, d3, a[2*j][0],   a[2*j][1],   a[2*j][2],   a[2*j][3],   bq[j].x, bq[j].y);
                mma_tf32(d0, d1, d2, d3, a[2*j+1][0], a[2*j+1][1], a[2*j+1][2], a[2*j+1][3], bq[j].z, bq[j].w);
            }
            // acc cols: n = 8c + 2t, 8c + 2t + 1 ; rows g / g+8
            float2 Bv = Bs2[c * 4 + t];
            int n = c * 8 + 2 * t;
            float v0 = fmaf(2.0f, d0, -Bv.x);
            float v1 = fmaf(2.0f, d1, -Bv.y);
            float v2 = fmaf(2.0f, d2, -Bv.x);
            float v3 = fmaf(2.0f, d3, -Bv.y);
            if (v0 > m1lo) { m2lo = m1lo; m1lo = v0; k1lo = n; }     else m2lo = fmaxf(m2lo, v0);
            if (v1 > m1lo) { m2lo = m1lo; m1lo = v1; k1lo = n + 1; } else m2lo = fmaxf(m2lo, v1);
            if (v2 > m1hi) { m2hi = m1hi; m1hi = v2; k1hi = n; }     else m2hi = fmaxf(m2hi, v2);
            if (v3 > m1hi) { m2hi = m1hi; m1hi = v3; k1hi = n + 1; } else m2hi = fmaxf(m2hi, v3);
        }

        // merge top-2 across the 4 lanes of the quad (cols are disjoint)
        #pragma unroll
        for (int off = 1; off <= 2; off <<= 1) {
            float om1 = __shfl_xor_sync(0xffffffffu, m1lo, off);
            float om2 = __shfl_xor_sync(0xffffffffu, m2lo, off);
            int   ok1 = __shfl_xor_sync(0xffffffffu, k1lo, off);
            if (om1 > m1lo) { m2lo = fmaxf(m1lo, om2); m1lo = om1; k1lo = ok1; }
            else            { m2lo = fmaxf(m2lo, om1); }
            om1 = __shfl_xor_sync(0xffffffffu, m1hi, off);
            om2 = __shfl_xor_sync(0xffffffffu, m2hi, off);
            ok1 = __shfl_xor_sync(0xffffffffu, k1hi, off);
            if (om1 > m1hi) { m2hi = fmaxf(m1hi, om2); m1hi = om1; k1hi = ok1; }
            else            { m2hi = fmaxf(m2hi, om1); }
        }
        if (t == 0) {
            sk1[row0 + g]     = k1lo;  sgp[row0 + g]     = m1lo - m2lo;
            sk1[row0 + g + 8] = k1hi;  sgp[row0 + g + 8] = m1hi - m2hi;
        }
    }
    __syncthreads();

    // ---- phase 2: exact x reload, margin test, outputs / flag list ----
    float lsum = 0.0f;
    if (tid < 128) {
        const int p  = tile * 128 + tid;
        const int bb = p >> 12, hw = p & 4095;
        const float* xp = X + (size_t)bb * (D_DIM * HW) + hw;
        float x[D_DIM], sab = 0.0f, A2 = 0.0f;
        #pragma unroll
        for (int d = 0; d < D_DIM; d++) {
            x[d] = xp[(size_t)d * HW];
            sab += fabsf(x[d]);
            A2  += x[d] * x[d];
        }
        float margin = 6e-6f * sab + 4e-7f * A2 + 5e-5f;
        int   k1   = sk1[tid];
        bool  flag = (sgp[tid] <= margin);

        if (!flag) {
            const float4* wp = (const float4*)(W + (size_t)k1 * D_DIM);
            float* qb = out_q ? out_q + (size_t)bb * (D_DIM * HW) + hw : nullptr;
            #pragma unroll
            for (int q4 = 0; q4 < 16; q4++) {
                float4 w4 = wp[q4];
                float wv[4] = {w4.x, w4.y, w4.z, w4.w};
                #pragma unroll
                for (int j = 0; j < 4; j++) {
                    int d = q4 * 4 + j;
                    float diff = wv[j] - x[d];          // fl(q - x), as reference
                    if (qb) qb[(size_t)d * HW] = x[d] + diff;
                    lsum += diff * diff;
                }
            }
            if (out_idx_f) out_idx_f[p] = (float)k1;
        } else {
            int pos = atomicAdd(&g_flag_cnt, 1);
            g_list[pos] = ((unsigned)p << 10) | (unsigned)k1;
        }
        #pragma unroll
        for (int off = 16; off > 0; off >>= 1)
            lsum += __shfl_xor_sync(0xffffffffu, lsum, off);
        if ((tid & 31) == 0) atomicAdd(&g_loss_acc, (double)lsum);
    }

    // ---- enc rows (fused zero-fill + one-hot), ALIGNMENT-SAFE wide stores ----
    // out_enc may be float-misaligned for float4 (base = d_out + 1 + NQ floats).
    // Per row: h head scalars until 16B boundary, then aligned float4 groups, tail scalars.
    if (out_enc) {
        const int r = (int)(((uintptr_t)out_enc >> 2) & 3);   // base float index mod 4
        const int h = (4 - r) & 3;                            // head scalars per row
        const int ngroups = (K_CODES - h) >> 2;               // aligned float4 groups
        for (int i = tid; i < 128 * 128; i += 256) {
            int row = i >> 7, q = i & 127;
            int b = sk1[row];
            float* rb = out_enc + (size_t)(tile * 128 + row) * K_CODES;
            if (q < ngroups) {
                int e0 = h + 4 * q;
                float4 v = make_float4(0.f, 0.f, 0.f, 0.f);
                int dk = b - e0;
                if ((unsigned)dk < 4u) ((float*)&v)[dk] = 1.0f;
                *(float4*)(rb + e0) = v;
            } else if (q == ngroups) {
                #pragma unroll
                for (int e = 0; e < 3; e++)
                    if (e < h) rb[e] = (b == e) ? 1.0f : 0.0f;
                for (int e = h + 4 * ngroups; e < K_CODES; e++)
                    rb[e] = (b == e) ? 1.0f : 0.0f;
            }
        }
    }
}

// ---------------- exact rescore: one warp per flagged pixel ----------------
#define RS_BLOCKS 64
#define RS_WARPS  (RS_BLOCKS * 8)
#define RS_SMEM   ((K_CODES * 65 + K_CODES) * 4)   // 135168

__global__ void __launch_bounds__(256, 1)
rescore_kernel(const float* __restrict__ X, const float* __restrict__ W,
               float* __restrict__ out_q, float* __restrict__ out_enc,
               float* __restrict__ out_idx_f)
{
    const int cnt = g_flag_cnt;
    if ((int)blockIdx.x * 8 >= cnt) return;

    extern __shared__ float sm[];
    float* wp  = sm;                     // [k*65 + d], stride-65 conflict-free
    float* Bsp = sm + K_CODES * 65;

    const int tid = threadIdx.x, lid = tid & 31;
    for (int i = tid; i < K_CODES * D_DIM; i += 256) {
        int k = i >> 6, d = i & 63;
        wp[k * 65 + d] = W[i];
    }
    for (int i = tid; i < K_CODES; i += 256) Bsp[i] = g_Bs[i];
    __syncthreads();

    for (int it = blockIdx.x * 8 + (tid >> 5); it < cnt; it += RS_WARPS) {
        unsigned e = g_list[it];
        int p = (int)(e >> 10), k1p = (int)(e & 1023u);
        int bb = p >> 12, hw = p & 4095;
        const float* xp = X + (size_t)bb * (D_DIM * HW) + hw;

        float x[D_DIM];
        #pragma unroll
        for (int d = 0; d < D_DIM; d++) x[d] = xp[(size_t)d * HW];
        float A = 0.0f;
        #pragma unroll
        for (int d = 0; d < D_DIM; d++) A += x[d] * x[d];

        // exact reference-order scan: lane handles k = lid + 32c
        float bd = CUDART_INF_F; int bk = 0;
        for (int c = 0; c < 16; c++) {
            int k = lid + (c << 5);
            const float* wr = wp + k * 65;
            float s = 0.0f;
            #pragma unroll
            for (int d = 0; d < D_DIM; d++) s += x[d] * wr[d];  // fused fmaf, d ascending
            float t = (A + Bsp[k]) - 2.0f * s;
            if (t < bd) { bd = t; bk = k; }
        }
        // lexicographic (dist, k) min across lanes == global first-min
        #pragma unroll
        for (int off = 16; off > 0; off >>= 1) {
            float od = __shfl_xor_sync(0xffffffffu, bd, off);
            int   ok = __shfl_xor_sync(0xffffffffu, bk, off);
            if (od < bd || (od == bd && ok < bk)) { bd = od; bk = ok; }
        }

        if (lid == 0) {
            if (out_idx_f) out_idx_f[p] = (float)bk;
            if (out_enc && bk != k1p) {
                out_enc[(size_t)p * K_CODES + k1p] = 0.0f;   // scalar, any alignment
                out_enc[(size_t)p * K_CODES + bk]  = 1.0f;
            }
        }
        float lsum = 0.0f;
        float* qb = out_q ? out_q + (size_t)bb * (D_DIM * HW) + hw : nullptr;
        #pragma unroll
        for (int j = 0; j < 2; j++) {
            int d = lid + 32 * j;
            float diff = wp[bk * 65 + d] - x[d];
            if (qb) qb[(size_t)d * HW] = x[d] + diff;
            lsum += diff * diff;
        }
        #pragma unroll
        for (int off = 16; off > 0; off >>= 1)
            lsum += __shfl_xor_sync(0xffffffffu, lsum, off);
        if (lid == 0) atomicAdd(&g_loss_acc, (double)lsum);
    }
}

// ---------------- launch ----------------
extern "C" void kernel_launch(void* const* d_in, const int* in_sizes, int n_in,
                              void* d_out, int out_size)
{
    const float* X = (const float*)d_in[0];
    const float* W = (const float*)d_in[1];
    float* out = (float*)d_out;

    const long long os = (long long)out_size;
    const long long FULL    = 1LL + NQ + ENC_SZ + N_PIX;
    const long long NO_LOSS = (long long)NQ + ENC_SZ + N_PIX;

    float* p_loss = nullptr; float* p_q = nullptr;
    float* p_enc  = nullptr; float* p_idxf = nullptr;

    if (os == FULL) {
        p_loss = out; p_q = out + 1; p_enc = out + 1 + NQ;
        p_idxf = out + 1 + NQ + ENC_SZ;
    } else if (os == NO_LOSS) {
        p_q = out; p_enc = out + NQ; p_idxf = out + NQ + ENC_SZ;
    } else if (os == NQ) {
        p_q = out;
    } else if (os == 1) {
        p_loss = out;
    } else {
        p_loss = out; p_q = out + 1;
        if (os >= 1 + NQ + ENC_SZ) p_enc = out + 1 + NQ;
        if (os >= FULL) p_idxf = out + 1 + NQ + ENC_SZ;
    }

    cudaFuncSetAttribute(vq_mma_kernel,
                         cudaFuncAttributeMaxDynamicSharedMemorySize, SM_TOTAL);
    cudaFuncSetAttribute(rescore_kernel,
                         cudaFuncAttributeMaxDynamicSharedMemorySize, RS_SMEM);

    prep_bs_kernel<<<1, 512>>>(W);
    prep_frag_kernel<<<64, 512>>>(W);
    vq_mma_kernel<<<N_PIX / 128, 256, SM_TOTAL>>>(X, W, p_q, p_enc, p_idxf);
    rescore_kernel<<<RS_BLOCKS, 256, RS_SMEM>>>(X, W, p_q, p_enc, p_idxf);
    if (p_loss) finalize_kernel<<<1, 1>>>(p_loss);
}

// round 12
// speedup vs baseline: 1.5907x; 1.4488x over previous
#include <cuda_runtime.h>
#include <math_constants.h>
#include <cstdint>

#define D_DIM   64
#define K_CODES 512
#define HW      4096
#define N_PIX   131072              // 32*64*64
#define NQ      8388608             // 32*64*64*64
#define ENC_SZ  ((long long)N_PIX * K_CODES)   // 67108864

// ---------------- device globals (no allocation allowed) ----------------
__device__ double   g_loss_acc;
__device__ int      g_flag_cnt;
__device__ float    g_Bs[K_CODES];
__device__ __align__(16) uint32_t g_Wfrag[K_CODES * D_DIM]; // tf32 bits, B-frag order
__device__ unsigned g_list[N_PIX];

__device__ __forceinline__ uint32_t f2tf32(float f) {
    uint32_t o;
    asm("cvt.rna.tf32.f32 %0, %1;" : "=r"(o) : "f"(f));
    return o;
}

__device__ __forceinline__ void mma_tf32(float& d0, float& d1, float& d2, float& d3,
                                         uint32_t a0, uint32_t a1, uint32_t a2, uint32_t a3,
                                         uint32_t b0, uint32_t b1) {
    asm volatile(
        "mma.sync.aligned.m16n8k8.row.col.f32.tf32.tf32.f32 "
        "{%0,%1,%2,%3}, {%4,%5,%6,%7}, {%8,%9}, {%0,%1,%2,%3};"
        : "+f"(d0), "+f"(d1), "+f"(d2), "+f"(d3)
        : "r"(a0), "r"(a1), "r"(a2), "r"(a3), "r"(b0), "r"(b1));
}

// ---------------- prep kernels ----------------
__global__ void prep_bs_kernel(const float* __restrict__ W) {
    int k = threadIdx.x;             // 512 threads
    float b = 0.0f;
    #pragma unroll
    for (int d = 0; d < D_DIM; d++) { float w = W[k * D_DIM + d]; b += w * w; }
    g_Bs[k] = b;
    if (k == 0) { g_loss_acc = 0.0; g_flag_cnt = 0; }
}

// B fragment order (PTX mma.m16n8k8, B col-major 8x8 per step)
__global__ void prep_frag_kernel(const float* __restrict__ W) {
    int idx = blockIdx.x * 512 + threadIdx.x;   // 64 x 512 = 32768
    int v    = idx & 3;
    int lane = (idx >> 2) & 31;
    int j    = (idx >> 7) & 3;
    int c    = idx >> 9;
    int s  = 2 * j + (v >> 1);
    int k  = s * 8 + (lane & 3) + ((v & 1) ? 4 : 0);
    int n  = c * 8 + (lane >> 2);
    g_Wfrag[idx] = f2tf32(W[n * D_DIM + k]);
}

__global__ void finalize_kernel(float* out_loss) {
    *out_loss = (float)(2.0 * g_loss_acc / (double)NQ);
}

// ---------------- smem layout (bytes), main kernel: 256-pixel tile ----------------
#define SM_W     0               // 131072 : Wfrag (tf32 bits)
#define SM_BS    131072          //   2048 : ||e||^2
#define SM_XS    133120          //  66560 : x tile tf32, [256][65]
#define SM_K1    199680          //   1024 : per-pixel approx argmax
#define SM_GAP   200704          //   1024 : per-pixel top-2 gap
#define SM_TOTAL 201728

// ---------------- main kernel: 256 pixels / block, 16 warps ----------------
__global__ void __launch_bounds__(512, 1)
vq_mma_kernel(const float* __restrict__ X, const float* __restrict__ W,
              float* __restrict__ out_q, float* __restrict__ out_enc,
              float* __restrict__ out_idx_f)
{
    extern __shared__ char smem[];
    uint32_t* Wf  = (uint32_t*)(smem + SM_W);
    float*    Bss = (float*)(smem + SM_BS);
    uint32_t* xs  = (uint32_t*)(smem + SM_XS);
    int*      sk1 = (int*)(smem + SM_K1);
    float*    sgp = (float*)(smem + SM_GAP);

    const int tid  = threadIdx.x;
    const int lane = tid & 31, warp = tid >> 5;
    const int tile = blockIdx.x;                 // 512 tiles of 256 pixels
    const int bidx = tile >> 4;                  // 16 tiles per batch
    const int hw0  = (tile & 15) << 8;

    // stage codebook fragments (L2-resident, coalesced 16B)
    {
        const uint4* src = (const uint4*)g_Wfrag;
        uint4* dst = (uint4*)Wf;
        #pragma unroll
        for (int i = 0; i < 16; i++) dst[tid + 512 * i] = src[tid + 512 * i];
    }
    for (int i = tid; i < K_CODES; i += 512) Bss[i] = g_Bs[i];

    // stage x tile as tf32, [m][d] stride 65 (conflict-free STS)
    const float* Xb = X + (size_t)bidx * (D_DIM * HW) + hw0;
    for (int i = tid; i < 256 * D_DIM; i += 512) {
        int d = i >> 8, m = i & 255;
        xs[m * 65 + d] = f2tf32(Xb[(size_t)d * HW + m]);
    }
    __syncthreads();

    // ---- phase 1: per-warp 16 rows x 512 codes via mma.sync tf32 ----
    {
        const int g = lane >> 2, t = lane & 3;
        const int row0 = warp * 16;
        // A fragments (m16n8k8): a0(r=g,k=t) a1(r=g+8,k=t) a2(r=g,k=t+4) a3(r=g+8,k=t+4)
        uint32_t a[8][4];
        #pragma unroll
        for (int s = 0; s < 8; s++) {
            int klo = s * 8 + t;
            a[s][0] = xs[(row0 + g)     * 65 + klo];
            a[s][1] = xs[(row0 + g + 8) * 65 + klo];
            a[s][2] = xs[(row0 + g)     * 65 + klo + 4];
            a[s][3] = xs[(row0 + g + 8) * 65 + klo + 4];
        }

        float m1lo = -CUDART_INF_F, m2lo = -CUDART_INF_F;
        float m1hi = -CUDART_INF_F, m2hi = -CUDART_INF_F;
        int   k1lo = 0, k1hi = 0;

        const uint4*  Wf4 = (const uint4*)Wf;
        const float2* Bs2 = (const float2*)Bss;

        #pragma unroll 2
        for (int c = 0; c < 64; c++) {
            uint4 bq[4];
            #pragma unroll
            for (int j = 0; j < 4; j++) bq[j] = Wf4[(c * 4 + j) * 32 + lane];

            float d0 = 0.f, d1 = 0.f, d2 = 0.f, d3 = 0.f;
            #pragma unroll
            for (int j = 0; j < 4; j++) {
                mma_tf32(d0, d1, d2, d3, a[2*j][0],   a[2*j][1],   a[2*j][2],   a[2*j][3],   bq[j].x, bq[j].y);
                mma_tf32(d0, d1, d2, d3, a[2*j+1][0], a[2*j+1][1], a[2*j+1][2], a[2*j+1][3], bq[j].z, bq[j].w);
            }
            // acc cols: n = 8c + 2t, 8c + 2t + 1 ; rows g / g+8
            float2 Bv = Bs2[c * 4 + t];
            int n = c * 8 + 2 * t;
            float v0 = fmaf(2.0f, d0, -Bv.x);
            float v1 = fmaf(2.0f, d1, -Bv.y);
            float v2 = fmaf(2.0f, d2, -Bv.x);
            float v3 = fmaf(2.0f, d3, -Bv.y);
            if (v0 > m1lo) { m2lo = m1lo; m1lo = v0; k1lo = n; }     else m2lo = fmaxf(m2lo, v0);
            if (v1 > m1lo) { m2lo = m1lo; m1lo = v1; k1lo = n + 1; } else m2lo = fmaxf(m2lo, v1);
            if (v2 > m1hi) { m2hi = m1hi; m1hi = v2; k1hi = n; }     else m2hi = fmaxf(m2hi, v2);
            if (v3 > m1hi) { m2hi = m1hi; m1hi = v3; k1hi = n + 1; } else m2hi = fmaxf(m2hi, v3);
        }

        // merge top-2 across the 4 lanes of the quad (cols are disjoint)
        #pragma unroll
        for (int off = 1; off <= 2; off <<= 1) {
            float om1 = __shfl_xor_sync(0xffffffffu, m1lo, off);
            float om2 = __shfl_xor_sync(0xffffffffu, m2lo, off);
            int   ok1 = __shfl_xor_sync(0xffffffffu, k1lo, off);
            if (om1 > m1lo) { m2lo = fmaxf(m1lo, om2); m1lo = om1; k1lo = ok1; }
            else            { m2lo = fmaxf(m2lo, om1); }
            om1 = __shfl_xor_sync(0xffffffffu, m1hi, off);
            om2 = __shfl_xor_sync(0xffffffffu, m2hi, off);
            ok1 = __shfl_xor_sync(0xffffffffu, k1hi, off);
            if (om1 > m1hi) { m2hi = fmaxf(m1hi, om2); m1hi = om1; k1hi = ok1; }
            else            { m2hi = fmaxf(m2hi, om1); }
        }
        if (t == 0) {
            sk1[row0 + g]     = k1lo;  sgp[row0 + g]     = m1lo - m2lo;
            sk1[row0 + g + 8] = k1hi;  sgp[row0 + g + 8] = m1hi - m2hi;
        }
    }
    __syncthreads();

    // ---- phase 2 (warps 0-7): exact x reload, margin test, outputs / flag list ----
    if (tid < 256) {
        float lsum = 0.0f;
        const int p  = tile * 256 + tid;
        const int bb = p >> 12, hw = p & 4095;
        const float* xp = X + (size_t)bb * (D_DIM * HW) + hw;
        float x[D_DIM], sab = 0.0f, A2 = 0.0f;
        #pragma unroll
        for (int d = 0; d < D_DIM; d++) {
            x[d] = xp[(size_t)d * HW];
            sab += fabsf(x[d]);
            A2  += x[d] * x[d];
        }
        float margin = 6e-6f * sab + 4e-7f * A2 + 5e-5f;
        int   k1   = sk1[tid];
        bool  flag = (sgp[tid] <= margin);

        if (!flag) {
            const float4* wp = (const float4*)(W + (size_t)k1 * D_DIM);
            float* qb = out_q ? out_q + (size_t)bb * (D_DIM * HW) + hw : nullptr;
            #pragma unroll
            for (int q4 = 0; q4 < 16; q4++) {
                float4 w4 = wp[q4];
                float wv[4] = {w4.x, w4.y, w4.z, w4.w};
                #pragma unroll
                for (int j = 0; j < 4; j++) {
                    int d = q4 * 4 + j;
                    float diff = wv[j] - x[d];          // fl(q - x), as reference
                    if (qb) qb[(size_t)d * HW] = x[d] + diff;
                    lsum += diff * diff;
                }
            }
            if (out_idx_f) out_idx_f[p] = (float)k1;
        } else {
            int pos = atomicAdd(&g_flag_cnt, 1);
            g_list[pos] = ((unsigned)p << 10) | (unsigned)k1;
        }
        #pragma unroll
        for (int off = 16; off > 0; off >>= 1)
            lsum += __shfl_xor_sync(0xffffffffu, lsum, off);
        if ((tid & 31) == 0) atomicAdd(&g_loss_acc, (double)lsum);
    }

    // ---- enc rows (fused zero-fill + one-hot), alignment-safe wide stores ----
    // warps 8-15 arrive here immediately and overlap with phase 2.
    if (out_enc) {
        const int r = (int)(((uintptr_t)out_enc >> 2) & 3);
        const int h = (4 - r) & 3;
        const int ngroups = (K_CODES - h) >> 2;
        for (int i = tid; i < 256 * 128; i += 512) {
            int row = i >> 7, q = i & 127;
            int b = sk1[row];
            float* rb = out_enc + (size_t)(tile * 256 + row) * K_CODES;
            if (q < ngroups) {
                int e0 = h + 4 * q;
                float4 v = make_float4(0.f, 0.f, 0.f, 0.f);
                int dk = b - e0;
                if ((unsigned)dk < 4u) ((float*)&v)[dk] = 1.0f;
                *(float4*)(rb + e0) = v;
            } else if (q == ngroups) {
                #pragma unroll
                for (int e = 0; e < 3; e++)
                    if (e < h) rb[e] = (b == e) ? 1.0f : 0.0f;
                for (int e = h + 4 * ngroups; e < K_CODES; e++)
                    rb[e] = (b == e) ? 1.0f : 0.0f;
            }
        }
    }
}

// ---------------- exact rescore: 4 pixels per warp, register-blocked ----------------
// smem: w2 [d][k] 131072 B + Bs 2048 B + per-warp x buffers 8*1024 B
#define RS_BLOCKS 148
#define RS_SMEM   (131072 + 2048 + 8 * 1024)

__global__ void __launch_bounds__(256, 1)
rescore_kernel(const float* __restrict__ X, const float* __restrict__ W,
               float* __restrict__ out_q, float* __restrict__ out_enc,
               float* __restrict__ out_idx_f)
{
    const int cnt = g_flag_cnt;
    if (cnt == 0) return;
    const int ngrp = (cnt + 3) >> 2;
    if ((int)blockIdx.x * 8 >= ngrp) return;

    extern __shared__ float sm[];
    float* w2  = sm;                      // [d*512 + k]
    float* Bsp = sm + D_DIM * K_CODES;    // 512
    float* xwb = Bsp + K_CODES;           // [warp][d*4 + j], 256 floats/warp

    const int tid = threadIdx.x, lid = tid & 31, warp = tid >> 5;
    float* xw = xwb + warp * 256;

    for (int i = tid; i < K_CODES * D_DIM; i += 256) {
        int k = i >> 6, d = i & 63;
        w2[d * K_CODES + k] = W[i];       // transpose to [d][k]
    }
    for (int i = tid; i < K_CODES; i += 256) Bsp[i] = g_Bs[i];
    __syncthreads();

    for (int g = blockIdx.x * 8 + warp; g < ngrp; g += RS_BLOCKS * 8) {
        // gather 4 entries (pad with entry 0 of the group)
        int base = g * 4;
        unsigned e0 = g_list[base];
        int pe[4], ke[4]; bool valid[4];
        #pragma unroll
        for (int j = 0; j < 4; j++) {
            valid[j] = (base + j < cnt);
            unsigned e = valid[j] ? g_list[base + j] : e0;
            pe[j] = (int)(e >> 10); ke[j] = (int)(e & 1023u);
        }

        // stage x for the 4 pixels: xw[d*4 + j]
        for (int idx = lid; idx < 256; idx += 32) {
            int d = idx >> 2, j = idx & 3;
            int p = pe[j], bb = p >> 12, hw = p & 4095;
            xw[idx] = X[(size_t)bb * (D_DIM * HW) + (size_t)d * HW + hw];
        }
        __syncwarp();

        // A[j] = ||x||^2, exact ascending (lane j computes pixel j)
        float Aj = 0.0f;
        if (lid < 4) {
            #pragma unroll
            for (int d = 0; d < D_DIM; d++) {
                float xv = xw[d * 4 + lid];
                Aj += xv * xv;
            }
        }
        float A[4];
        #pragma unroll
        for (int j = 0; j < 4; j++) A[j] = __shfl_sync(0xffffffffu, Aj, j);

        // 64 accumulators: s[j][i], code k = lid + 32i; fmaf ascending in d
        float s[4][16];
        #pragma unroll
        for (int j = 0; j < 4; j++)
            #pragma unroll
            for (int i = 0; i < 16; i++) s[j][i] = 0.0f;

        for (int d = 0; d < D_DIM; d++) {
            float xv[4];
            #pragma unroll
            for (int j = 0; j < 4; j++) xv[j] = xw[d * 4 + j];   // broadcast
            const float* wr = w2 + d * K_CODES + lid;            // conflict-free
            #pragma unroll
            for (int i = 0; i < 16; i++) {
                float wv = wr[i * 32];
                #pragma unroll
                for (int j = 0; j < 4; j++) s[j][i] = fmaf(xv[j], wv, s[j][i]);
            }
        }

        // per pixel: first strict min over k (i ascending => k ascending in lane)
        #pragma unroll
        for (int j = 0; j < 4; j++) {
            float bd = CUDART_INF_F; int bk = 0;
            #pragma unroll
            for (int i = 0; i < 16; i++) {
                int k = lid + (i << 5);
                float t = (A[j] + Bsp[k]) - 2.0f * s[j][i];
                if (t < bd) { bd = t; bk = k; }
            }
            #pragma unroll
            for (int off = 16; off > 0; off >>= 1) {
                float od = __shfl_xor_sync(0xffffffffu, bd, off);
                int   ok = __shfl_xor_sync(0xffffffffu, bk, off);
                if (od < bd || (od == bd && ok < bk)) { bd = od; bk = ok; }
            }

            float lsum = 0.0f;
            if (valid[j]) {
                int p = pe[j], bb = p >> 12, hw = p & 4095;
                if (lid == 0) {
                    if (out_idx_f) out_idx_f[p] = (float)bk;
                    if (out_enc && bk != ke[j]) {
                        out_enc[(size_t)p * K_CODES + ke[j]] = 0.0f;
                        out_enc[(size_t)p * K_CODES + bk]   = 1.0f;
                    }
                }
                float* qb = out_q ? out_q + (size_t)bb * (D_DIM * HW) + hw : nullptr;
                #pragma unroll
                for (int u = 0; u < 2; u++) {
                    int d = lid + 32 * u;
                    float diff = W[(size_t)bk * D_DIM + d] - xw[d * 4 + j];  // coalesced W read
                    if (qb) qb[(size_t)d * HW] = xw[d * 4 + j] + diff;
                    lsum += diff * diff;
                }
            }
            #pragma unroll
            for (int off = 16; off > 0; off >>= 1)
                lsum += __shfl_xor_sync(0xffffffffu, lsum, off);
            if (lid == 0 && valid[j]) atomicAdd(&g_loss_acc, (double)lsum);
        }
        __syncwarp();
    }
}

// ---------------- launch ----------------
extern "C" void kernel_launch(void* const* d_in, const int* in_sizes, int n_in,
                              void* d_out, int out_size)
{
    const float* X = (const float*)d_in[0];
    const float* W = (const float*)d_in[1];
    float* out = (float*)d_out;

    const long long os = (long long)out_size;
    const long long FULL    = 1LL + NQ + ENC_SZ + N_PIX;
    const long long NO_LOSS = (long long)NQ + ENC_SZ + N_PIX;

    float* p_loss = nullptr; float* p_q = nullptr;
    float* p_enc  = nullptr; float* p_idxf = nullptr;

    if (os == FULL) {
        p_loss = out; p_q = out + 1; p_enc = out + 1 + NQ;
        p_idxf = out + 1 + NQ + ENC_SZ;
    } else if (os == NO_LOSS) {
        p_q = out; p_enc = out + NQ; p_idxf = out + NQ + ENC_SZ;
    } else if (os == NQ) {
        p_q = out;
    } else if (os == 1) {
        p_loss = out;
    } else {
        p_loss = out; p_q = out + 1;
        if (os >= 1 + NQ + ENC_SZ) p_enc = out + 1 + NQ;
        if (os >= FULL) p_idxf = out + 1 + NQ + ENC_SZ;
    }

    cudaFuncSetAttribute(vq_mma_kernel,
                         cudaFuncAttributeMaxDynamicSharedMemorySize, SM_TOTAL);
    cudaFuncSetAttribute(rescore_kernel,
                         cudaFuncAttributeMaxDynamicSharedMemorySize, RS_SMEM);

    prep_bs_kernel<<<1, 512>>>(W);
    prep_frag_kernel<<<64, 512>>>(W);
    vq_mma_kernel<<<N_PIX / 256, 512, SM_TOTAL>>>(X, W, p_q, p_enc, p_idxf);
    rescore_kernel<<<RS_BLOCKS, 256, RS_SMEM>>>(X, W, p_q, p_enc, p_idxf);
    if (p_loss) finalize_kernel<<<1, 1>>>(p_loss);
}